// round 2
// baseline (speedup 1.0000x reference)
#include <cuda_runtime.h>
#include <math.h>

#define BATCH   8192
#define NSITES  256
#define DIM     128
#define NOUT    10
#define TS      64      // samples per CTA
#define NTHREADS 256
#define MIDSITES 254

// Scratch: feature map, site-major layout for coalesced per-site reads.
__device__ float g_phiC[NSITES * BATCH];
__device__ float g_phiS[NSITES * BATCH];

// ---------------------------------------------------------------------------
// Kernel 1: per-sample min/max normalization + (cos, sin) feature map.
// One block per sample, thread n handles site n.
// ---------------------------------------------------------------------------
__global__ void phi_kernel(const float* __restrict__ x) {
    const int b = blockIdx.x;
    const int n = threadIdx.x;
    const float v = x[b * NSITES + n];

    float mn = v, mx = v;
    #pragma unroll
    for (int off = 16; off > 0; off >>= 1) {
        mn = fminf(mn, __shfl_xor_sync(0xffffffffu, mn, off));
        mx = fmaxf(mx, __shfl_xor_sync(0xffffffffu, mx, off));
    }
    __shared__ float smn[8], smx[8];
    const int w = n >> 5, lane = n & 31;
    if (lane == 0) { smn[w] = mn; smx[w] = mx; }
    __syncthreads();
    mn = smn[0]; mx = smx[0];
    #pragma unroll
    for (int i = 1; i < 8; i++) {
        mn = fminf(mn, smn[i]);
        mx = fmaxf(mx, smx[i]);
    }
    const float ang = 1.57079632679489662f * (v - mn) / (mx - mn + 1e-6f);
    g_phiC[n * BATCH + b] = cosf(ang);
    g_phiS[n * BATCH + b] = sinf(ang);
}

// ---------------------------------------------------------------------------
// Kernel 2: MPS contraction. One CTA carries TS=64 samples through all sites.
// Per site:  left'[s][r] = sum_l left[s][l] * (M0[l][r]*c_s + M1[l][r]*s_s)
// M (128KB fp32) staged in smem per site; left (64x128) lives in smem.
// Thread tile: 8 samples x 4 outputs.
// ---------------------------------------------------------------------------
extern __shared__ float sm[];

__global__ __launch_bounds__(NTHREADS, 1)
void mps_kernel(const float* __restrict__ first,
                const float* __restrict__ mid,
                const float* __restrict__ last,
                const float* __restrict__ wlin,
                const float* __restrict__ blin,
                float* __restrict__ out) {
    float* W     = sm;                       // [256][128]  (k = 2l+d)
    float* Lf    = sm + 2 * DIM * DIM;       // [TS][128]
    float* sC    = Lf + TS * DIM;            // [TS]
    float* sS    = sC + TS;                  // [TS]
    float* sLast = sS + TS;                  // [256]

    const int b0  = blockIdx.x * TS;
    const int tid = threadIdx.x;
    const int tx  = tid & 31;                // output-column group
    const int ty  = tid >> 5;                // sample group
    const int r0  = tx * 4;
    const int sbase = ty * 8;

    // --- init left from site 0: left[s][r] = first[0][r]*c + first[1][r]*s ---
    for (int idx = tid; idx < TS * DIM; idx += NTHREADS) {
        const int s = idx >> 7, r = idx & 127;
        const float c0 = g_phiC[b0 + s];     // site 0
        const float s0 = g_phiS[b0 + s];
        Lf[idx] = first[r] * c0 + first[DIM + r] * s0;
    }
    // --- preload W(0) and phi(site 1) ---
    {
        const float4* src = (const float4*)mid;
        float4* dst = (float4*)W;
        #pragma unroll 8
        for (int idx = tid; idx < 2 * DIM * DIM / 4; idx += NTHREADS)
            dst[idx] = src[idx];
        if (tid < TS)           sC[tid]      = g_phiC[1 * BATCH + b0 + tid];
        else if (tid < 2 * TS)  sS[tid - TS] = g_phiS[1 * BATCH + b0 + tid - TS];
    }
    __syncthreads();

    for (int site = 0; site < MIDSITES; ++site) {
        float c[8], s[8];
        #pragma unroll
        for (int j = 0; j < 8; j++) { c[j] = sC[sbase + j]; s[j] = sS[sbase + j]; }

        float acc[8][4];
        #pragma unroll
        for (int j = 0; j < 8; j++)
            #pragma unroll
            for (int k = 0; k < 4; k++) acc[j][k] = 0.0f;

        const float* Wr = W + r0;
        #pragma unroll 4
        for (int l = 0; l < DIM; ++l) {
            const float4 w0 = *(const float4*)(Wr + (2 * l) * DIM);
            const float4 w1 = *(const float4*)(Wr + (2 * l + 1) * DIM);
            #pragma unroll
            for (int j = 0; j < 8; j++) {
                const float a  = Lf[(sbase + j) * DIM + l];
                const float ac = a * c[j];
                const float as = a * s[j];
                acc[j][0] = fmaf(ac, w0.x, fmaf(as, w1.x, acc[j][0]));
                acc[j][1] = fmaf(ac, w0.y, fmaf(as, w1.y, acc[j][1]));
                acc[j][2] = fmaf(ac, w0.z, fmaf(as, w1.z, acc[j][2]));
                acc[j][3] = fmaf(ac, w0.w, fmaf(as, w1.w, acc[j][3]));
            }
        }
        __syncthreads();   // all reads of Lf / W for this site are done

        // write updated left
        #pragma unroll
        for (int j = 0; j < 8; j++) {
            float4 v = make_float4(acc[j][0], acc[j][1], acc[j][2], acc[j][3]);
            *(float4*)&Lf[(sbase + j) * DIM + r0] = v;
        }
        // stage next site's W + phi (or the final-site data)
        if (site < MIDSITES - 1) {
            const float4* src = (const float4*)(mid + (size_t)(site + 1) * (2 * DIM * DIM));
            float4* dst = (float4*)W;
            #pragma unroll 8
            for (int idx = tid; idx < 2 * DIM * DIM / 4; idx += NTHREADS)
                dst[idx] = src[idx];
            const int ph = site + 2;
            if (tid < TS)           sC[tid]      = g_phiC[ph * BATCH + b0 + tid];
            else if (tid < 2 * TS)  sS[tid - TS] = g_phiS[ph * BATCH + b0 + tid - TS];
        } else {
            sLast[tid] = last[tid];   // 256 floats, one per thread
            if (tid < TS)           sC[tid]      = g_phiC[(NSITES - 1) * BATCH + b0 + tid];
            else if (tid < 2 * TS)  sS[tid - TS] = g_phiS[(NSITES - 1) * BATCH + b0 + tid - TS];
        }
        __syncthreads();
    }

    // --- final contraction + linear head ---
    if (tid < TS) {
        const float cL = sC[tid], sL = sS[tid];
        float acc = 0.0f;
        #pragma unroll 4
        for (int l = 0; l < DIM; ++l)
            acc = fmaf(Lf[tid * DIM + l],
                       fmaf(sLast[2 * l], cL, sLast[2 * l + 1] * sL), acc);
        #pragma unroll
        for (int o = 0; o < NOUT; o++)
            out[(b0 + tid) * NOUT + o] = fmaf(acc, wlin[o], blin[o]);
    }
}

// ---------------------------------------------------------------------------
extern "C" void kernel_launch(void* const* d_in, const int* in_sizes, int n_in,
                              void* d_out, int out_size) {
    const float* x     = (const float*)d_in[0];
    const float* first = (const float*)d_in[1];
    const float* mid   = (const float*)d_in[2];
    const float* last  = (const float*)d_in[3];
    const float* wlin  = (const float*)d_in[4];
    const float* blin  = (const float*)d_in[5];
    float* out = (float*)d_out;

    const int smem_bytes = (2 * DIM * DIM + TS * DIM + 2 * TS + 256) * sizeof(float);
    cudaFuncSetAttribute(mps_kernel, cudaFuncAttributeMaxDynamicSharedMemorySize,
                         smem_bytes);

    phi_kernel<<<BATCH, NSITES>>>(x);
    mps_kernel<<<BATCH / TS, NTHREADS, smem_bytes>>>(first, mid, last, wlin, blin, out);
}

// round 3
// speedup vs baseline: 1.1764x; 1.1764x over previous
#include <cuda_runtime.h>
#include <math.h>

#define BATCH   8192
#define NSITES  256
#define DIM     128
#define NOUT    10
#define TS      64      // samples per CTA
#define NTHREADS 256
#define MIDSITES 254

// Scratch: feature map, site-major layout for coalesced per-site reads.
__device__ float g_phiC[NSITES * BATCH];
__device__ float g_phiS[NSITES * BATCH];

// ---------------------------------------------------------------------------
// f32x2 packed-math helpers (sm_10x; ptxas never auto-fuses these)
// ---------------------------------------------------------------------------
__device__ __forceinline__ unsigned long long dup_f32x2(float a) {
    unsigned long long r;
    asm("mov.b64 %0, {%1, %1};" : "=l"(r) : "f"(a));
    return r;
}
__device__ __forceinline__ void ffma2(unsigned long long& d,
                                      unsigned long long a,
                                      unsigned long long b) {
    asm("fma.rn.f32x2 %0, %1, %2, %0;" : "+l"(d) : "l"(a), "l"(b));
}
__device__ __forceinline__ float2 unpack2(unsigned long long v) {
    float2 f;
    asm("mov.b64 {%0, %1}, %2;" : "=f"(f.x), "=f"(f.y) : "l"(v));
    return f;
}
__device__ __forceinline__ void lds_v2b64(unsigned long long& a,
                                          unsigned long long& b,
                                          unsigned smem_addr) {
    asm volatile("ld.shared.v2.b64 {%0, %1}, [%2];"
                 : "=l"(a), "=l"(b) : "r"(smem_addr));
}

// ---------------------------------------------------------------------------
// Kernel 1: per-sample min/max normalization + (cos, sin) feature map.
// ---------------------------------------------------------------------------
__global__ void phi_kernel(const float* __restrict__ x) {
    const int b = blockIdx.x;
    const int n = threadIdx.x;
    const float v = x[b * NSITES + n];

    float mn = v, mx = v;
    #pragma unroll
    for (int off = 16; off > 0; off >>= 1) {
        mn = fminf(mn, __shfl_xor_sync(0xffffffffu, mn, off));
        mx = fmaxf(mx, __shfl_xor_sync(0xffffffffu, mx, off));
    }
    __shared__ float smn[8], smx[8];
    const int w = n >> 5, lane = n & 31;
    if (lane == 0) { smn[w] = mn; smx[w] = mx; }
    __syncthreads();
    mn = smn[0]; mx = smx[0];
    #pragma unroll
    for (int i = 1; i < 8; i++) {
        mn = fminf(mn, smn[i]);
        mx = fmaxf(mx, smx[i]);
    }
    const float ang = 1.57079632679489662f * (v - mn) / (mx - mn + 1e-6f);
    g_phiC[n * BATCH + b] = cosf(ang);
    g_phiS[n * BATCH + b] = sinf(ang);
}

// ---------------------------------------------------------------------------
// Kernel 2: MPS contraction, restructured as two matvecs + phi combine:
//   P0 = Lf @ W0,  P1 = Lf @ W1,  Lf' = c*P0 + s*P1
// Inner loop uses packed fma.rn.f32x2 (32 FFMA2/l/thread vs 80 fma ops before).
// ---------------------------------------------------------------------------
extern __shared__ float sm[];

__global__ __launch_bounds__(NTHREADS, 1)
void mps_kernel(const float* __restrict__ first,
                const float* __restrict__ mid,
                const float* __restrict__ last,
                const float* __restrict__ wlin,
                const float* __restrict__ blin,
                float* __restrict__ out) {
    float* W     = sm;                       // [256][128]  (row = 2l+d)
    float* Lf    = sm + 2 * DIM * DIM;       // [TS][128]
    float* sC    = Lf + TS * DIM;            // [TS]
    float* sS    = sC + TS;                  // [TS]
    float* sLast = sS + TS;                  // [256]

    const int b0  = blockIdx.x * TS;
    const int tid = threadIdx.x;
    const int tx  = tid & 31;                // output-column group
    const int ty  = tid >> 5;                // sample group (warp)
    const int r0  = tx * 4;
    const int sbase = ty * 8;

    const unsigned W_base  = (unsigned)__cvta_generic_to_shared(W) + r0 * 4u;
    const unsigned Lf_base = (unsigned)__cvta_generic_to_shared(Lf);

    // --- init left from site 0 ---
    for (int idx = tid; idx < TS * DIM; idx += NTHREADS) {
        const int s = idx >> 7, r = idx & 127;
        const float c0 = g_phiC[b0 + s];
        const float s0 = g_phiS[b0 + s];
        Lf[idx] = first[r] * c0 + first[DIM + r] * s0;
    }
    // --- preload W(0) and phi(site 1) ---
    {
        const float4* src = (const float4*)mid;
        float4* dst = (float4*)W;
        #pragma unroll 8
        for (int idx = tid; idx < 2 * DIM * DIM / 4; idx += NTHREADS)
            dst[idx] = src[idx];
        if (tid < TS)           sC[tid]      = g_phiC[1 * BATCH + b0 + tid];
        else if (tid < 2 * TS)  sS[tid - TS] = g_phiS[1 * BATCH + b0 + tid - TS];
    }
    __syncthreads();

    for (int site = 0; site < MIDSITES; ++site) {
        float c[8], s[8];
        #pragma unroll
        for (int j = 0; j < 8; j++) { c[j] = sC[sbase + j]; s[j] = sS[sbase + j]; }

        // acc0 = P0 (pairs over r), acc1 = P1
        unsigned long long acc0[8][2], acc1[8][2];
        #pragma unroll
        for (int j = 0; j < 8; j++) {
            acc0[j][0] = 0ull; acc0[j][1] = 0ull;
            acc1[j][0] = 0ull; acc1[j][1] = 0ull;
        }

        #pragma unroll 1
        for (int lb = 0; lb < DIM; lb += 4) {
            // broadcast-load 4 l's of 'a' per sample
            float4 a4[8];
            #pragma unroll
            for (int j = 0; j < 8; j++)
                a4[j] = *(const float4*)(Lf + (sbase + j) * DIM + lb);

            #pragma unroll
            for (int li = 0; li < 4; ++li) {
                const int l = lb + li;
                unsigned long long w0a, w0b, w1a, w1b;
                lds_v2b64(w0a, w0b, W_base + (2 * l)     * (DIM * 4u));
                lds_v2b64(w1a, w1b, W_base + (2 * l + 1) * (DIM * 4u));
                #pragma unroll
                for (int j = 0; j < 8; j++) {
                    const float a = (li == 0) ? a4[j].x : (li == 1) ? a4[j].y
                                  : (li == 2) ? a4[j].z : a4[j].w;
                    const unsigned long long aa = dup_f32x2(a);
                    ffma2(acc0[j][0], aa, w0a);
                    ffma2(acc0[j][1], aa, w0b);
                    ffma2(acc1[j][0], aa, w1a);
                    ffma2(acc1[j][1], aa, w1b);
                }
            }
        }
        __syncthreads();   // all reads of Lf / W / sC / sS for this site done

        // epilogue: Lf' = c*P0 + s*P1
        #pragma unroll
        for (int j = 0; j < 8; j++) {
            const float2 p0a = unpack2(acc0[j][0]), p0b = unpack2(acc0[j][1]);
            const float2 p1a = unpack2(acc1[j][0]), p1b = unpack2(acc1[j][1]);
            float4 v;
            v.x = fmaf(c[j], p0a.x, s[j] * p1a.x);
            v.y = fmaf(c[j], p0a.y, s[j] * p1a.y);
            v.z = fmaf(c[j], p0b.x, s[j] * p1b.x);
            v.w = fmaf(c[j], p0b.y, s[j] * p1b.y);
            *(float4*)&Lf[(sbase + j) * DIM + r0] = v;
        }

        // stage next site's W + phi (or the final-site data)
        if (site < MIDSITES - 1) {
            const float4* src = (const float4*)(mid + (size_t)(site + 1) * (2 * DIM * DIM));
            float4* dst = (float4*)W;
            #pragma unroll 8
            for (int idx = tid; idx < 2 * DIM * DIM / 4; idx += NTHREADS)
                dst[idx] = src[idx];
            const int ph = site + 2;
            if (tid < TS)           sC[tid]      = g_phiC[ph * BATCH + b0 + tid];
            else if (tid < 2 * TS)  sS[tid - TS] = g_phiS[ph * BATCH + b0 + tid - TS];
        } else {
            sLast[tid] = last[tid];
            if (tid < TS)           sC[tid]      = g_phiC[(NSITES - 1) * BATCH + b0 + tid];
            else if (tid < 2 * TS)  sS[tid - TS] = g_phiS[(NSITES - 1) * BATCH + b0 + tid - TS];
        }
        __syncthreads();
    }

    // --- final contraction + linear head ---
    if (tid < TS) {
        const float cL = sC[tid], sL = sS[tid];
        float acc = 0.0f;
        #pragma unroll 4
        for (int l = 0; l < DIM; ++l)
            acc = fmaf(Lf[tid * DIM + l],
                       fmaf(sLast[2 * l], cL, sLast[2 * l + 1] * sL), acc);
        #pragma unroll
        for (int o = 0; o < NOUT; o++)
            out[(b0 + tid) * NOUT + o] = fmaf(acc, wlin[o], blin[o]);
    }
}

// ---------------------------------------------------------------------------
extern "C" void kernel_launch(void* const* d_in, const int* in_sizes, int n_in,
                              void* d_out, int out_size) {
    const float* x     = (const float*)d_in[0];
    const float* first = (const float*)d_in[1];
    const float* mid   = (const float*)d_in[2];
    const float* last  = (const float*)d_in[3];
    const float* wlin  = (const float*)d_in[4];
    const float* blin  = (const float*)d_in[5];
    float* out = (float*)d_out;

    const int smem_bytes = (2 * DIM * DIM + TS * DIM + 2 * TS + 256) * sizeof(float);
    cudaFuncSetAttribute(mps_kernel, cudaFuncAttributeMaxDynamicSharedMemorySize,
                         smem_bytes);

    phi_kernel<<<BATCH, NSITES>>>(x);
    mps_kernel<<<BATCH / TS, NTHREADS, smem_bytes>>>(first, mid, last, wlin, blin, out);
}